// round 10
// baseline (speedup 1.0000x reference)
#include <cuda_runtime.h>

#define T_STEPS 784
#define HDIM    110
#define G4      440
#define NTH     896
#define NCLS    10

// ---------- f32x2 packed helpers ----------
__device__ __forceinline__ unsigned long long pk2(float x, float y) {
    unsigned long long r;
    asm("mov.b64 %0, {%1,%2};" : "=l"(r) : "f"(x), "f"(y));
    return r;
}
__device__ __forceinline__ float2 upk2(unsigned long long a) {
    float2 r;
    asm("mov.b64 {%0,%1}, %2;" : "=f"(r.x), "=f"(r.y) : "l"(a));
    return r;
}
__device__ __forceinline__ void ff2(unsigned long long& acc,
                                    unsigned long long a,
                                    unsigned long long b) {
    asm("fma.rn.f32x2 %0, %1, %2, %0;" : "+l"(acc) : "l"(a), "l"(b));
}

// ---------- activations ----------
__device__ __forceinline__ float tanha(float x) {          // MUFU.TANH
    float r;
    asm("tanh.approx.f32 %0, %1;" : "=f"(r) : "f"(x));
    return r;
}
__device__ __forceinline__ float sigmf(float x) {          // fast gate sigmoid
    return fmaf(0.5f, tanha(0.5f * x), 0.5f);
}
__device__ __forceinline__ float sigm_precise(float x) {   // du decision path
    return __fdividef(1.0f, 1.0f + __expf(-x));
}

__global__ void zero_slot_kernel(float* o, int idx) { o[idx] = 0.0f; }

__global__ void __launch_bounds__(NTH, 1) skiplstm_kernel(
    const float* __restrict__ x,      // [B, T, 1]
    const float* __restrict__ Wih,    // [440, 1]
    const float* __restrict__ Whh,    // [440, 110]
    const float* __restrict__ bg,     // [440]
    const float* __restrict__ Wp,     // [1, 110]
    const float* __restrict__ bp_,    // [1]
    const float* __restrict__ h0,     // [110]
    const float* __restrict__ c0,     // [110]
    const float* __restrict__ Wfc,    // [10, 110]
    const float* __restrict__ bfc,    // [10]
    float* __restrict__ out,          // [B*10 + 1]
    int last_idx)
{
    __shared__ float sx[2][T_STEPS];                   // x sequences
    __shared__ __align__(16) float smh[2][112];        // h (pads 110,111 = 0)
    __shared__ __align__(16) float smc[2][112];        // c (pads = 0)
    __shared__ __align__(16) float2 sd[2][448];        // [half][row] = (b0, b1) partials
    __shared__ __align__(16) float stail[NTH][8];      // per-thread weight tail
    __shared__ float swp[112];                         // W_p (zero-padded)
    __shared__ float swih[G4];                         // W_ih column
    __shared__ float sbj[G4];                          // gate bias
    __shared__ float sflags[2];                        // activity flags

    const int tid  = threadIdx.x;
    const int warp = tid >> 5, lane = tid & 31;
    const int half = (warp >= 14) ? 1 : 0;             // which 56-float k-half
    const int row  = (warp - half * 14) * 32 + lane;   // gate row
    const bool gval = (row < G4);
    const int base = half * 56;
    const int b0g  = blockIdx.x * 2;

    for (int i = tid; i < T_STEPS; i += NTH) {
        sx[0][i] = x[b0g * T_STEPS + i];
        sx[1][i] = x[(b0g + 1) * T_STEPS + i];
    }
    for (int i = tid; i < 112; i += NTH) {
        float hv = (i < HDIM) ? h0[i] : 0.0f;
        float cv = (i < HDIM) ? c0[i] : 0.0f;
        smh[0][i] = hv; smh[1][i] = hv;
        smc[0][i] = cv; smc[1][i] = cv;
        swp[i] = (i < HDIM) ? Wp[i] : 0.0f;
    }
    if (tid < G4) {
        swih[tid] = Wih[tid];
        sbj[tid]  = bg[tid];
    }

    // ---- weights: 48 floats in regs, 8-float tail in smem ----
    unsigned long long w[24];
    {
        const float* wr = Whh + (gval ? row : 0) * HDIM;
#pragma unroll
        for (int j = 0; j < 24; j++)
            w[j] = gval ? pk2(wr[base + 2 * j], wr[base + 2 * j + 1]) : 0ull;
#pragma unroll
        for (int i = 0; i < 8; i++) {
            int f = base + 48 + i;
            stail[tid][i] = (gval && f < HDIM) ? wr[f] : 0.0f;
        }
    }
    const float bp = bp_[0];
    __syncthreads();

    // du-unit state (warp 27 lanes 24-31; harmless elsewhere)
    float u = 1.0f;
    bool  a = true;
    int   totu = 0;

    for (int t = 0; t < T_STEPS; t++) {
        if (gval) {
            // ======== GEMV: my 56-float half-row x both batch lanes ========
            const ulonglong2* hq0 = ((const ulonglong2*)smh[0]) + half * 14;
            const ulonglong2* hq1 = ((const ulonglong2*)smh[1]) + half * 14;
            ulonglong2 t01 = *(const ulonglong2*)&stail[tid][0];
            ulonglong2 t23 = *(const ulonglong2*)&stail[tid][4];
            unsigned long long a0 = 0ull, a1 = 0ull;
#pragma unroll
            for (int jj = 0; jj < 12; jj++) {
                ulonglong2 h0v = hq0[jj];
                ulonglong2 h1v = hq1[jj];
                ff2(a0, w[2 * jj],     h0v.x);
                ff2(a0, w[2 * jj + 1], h0v.y);
                ff2(a1, w[2 * jj],     h1v.x);
                ff2(a1, w[2 * jj + 1], h1v.y);
            }
            {   // tail k: floats base+48 .. base+55 (half1 top = zero pads)
                ulonglong2 h0v = hq0[12], h1v = hq1[12];
                ff2(a0, t01.x, h0v.x); ff2(a0, t01.y, h0v.y);
                ff2(a1, t01.x, h1v.x); ff2(a1, t01.y, h1v.y);
                h0v = hq0[13]; h1v = hq1[13];
                ff2(a0, t23.x, h0v.x); ff2(a0, t23.y, h0v.y);
                ff2(a1, t23.x, h1v.x); ff2(a1, t23.y, h1v.y);
            }
            float2 v0 = upk2(a0), v1 = upk2(a1);
            float val0 = v0.x + v0.y;
            float val1 = v1.x + v1.y;
            if (half == 0) {                       // add x*Wih + b once
                float wi = swih[row], bj = sbj[row];
                val0 += fmaf(sx[0][t], wi, bj);
                val1 += fmaf(sx[1][t], wi, bj);
            }
            sd[half][row] = make_float2(val0, val1);
        } else if (warp == 27) {
            // ======== du unit: lanes 24-31 of warp 27 (overlaps GEMV) ======
            const int idx = lane - 24;             // 0..7
            const int b   = idx >> 2, l4 = idx & 3;
            if (t > 0) {
                float p = 0.0f;
                for (int d = l4; d < HDIM; d += 4)
                    p += smc[b][d] * swp[d];
                p += __shfl_xor_sync(0xff000000u, p, 1);
                p += __shfl_xor_sync(0xff000000u, p, 2);
                float du = sigm_precise(p + bp);
                u = a ? du : u + fminf(du, 1.0f - u);
                a = (rintf(u) != 0.0f);
            }
            totu += a ? 1 : 0;
            if (l4 == 0) sflags[b] = a ? 1.0f : 0.0f;
        }
        __syncthreads();

        // ======== pointwise: combine halves + LSTM cell (warps 0-7) =======
        if (tid < 256) {
            const int b = tid >> 7;
            const int d = tid & 127;
            if (sflags[b] != 0.0f && d < HDIM) {
                const float* sdf = (const float*)sd;   // [half*896 + row*2 + b]
                float pi = sdf[(d)        * 2 + b] + sdf[896 + (d)        * 2 + b];
                float pf = sdf[(HDIM + d) * 2 + b] + sdf[896 + (HDIM + d) * 2 + b];
                float pg = sdf[(2*HDIM+d) * 2 + b] + sdf[896 + (2*HDIM+d) * 2 + b];
                float po = sdf[(3*HDIM+d) * 2 + b] + sdf[896 + (3*HDIM+d) * 2 + b];
                float i_ = sigmf(pi), f_ = sigmf(pf);
                float g_ = tanha(pg), o_ = sigmf(po);
                float cn = f_ * smc[b][d] + i_ * g_;
                smc[b][d] = cn;
                smh[b][d] = o_ * tanha(cn);
            }
        }
        __syncthreads();
    }

    // ---- FC head ----
    for (int pi = warp; pi < 2 * NCLS; pi += NTH / 32) {
        const int b = pi / NCLS, cls = pi % NCLS;
        const float* wf = Wfc + cls * HDIM;
        float s = 0.0f;
        for (int d = lane; d < HDIM; d += 32) s += smh[b][d] * wf[d];
#pragma unroll
        for (int off = 16; off; off >>= 1)
            s += __shfl_xor_sync(0xffffffffu, s, off);
        if (lane == 0) out[(b0g + b) * NCLS + cls] = s + bfc[cls];
    }

    // total_u: lane 24 holds batch0 count, lane 28 batch1 (exact int floats)
    if (warp == 27 && (lane == 24 || lane == 28))
        atomicAdd(&out[last_idx], (float)totu);
}

extern "C" void kernel_launch(void* const* d_in, const int* in_sizes, int n_in,
                              void* d_out, int out_size) {
    const float* x    = (const float*)d_in[0];
    const float* Wih  = (const float*)d_in[1];
    const float* Whh  = (const float*)d_in[2];
    const float* bg   = (const float*)d_in[3];
    const float* Wp   = (const float*)d_in[4];
    const float* bp   = (const float*)d_in[5];
    const float* h0   = (const float*)d_in[6];
    const float* c0   = (const float*)d_in[7];
    const float* Wfc  = (const float*)d_in[8];
    const float* bfc  = (const float*)d_in[9];
    float* out = (float*)d_out;

    const int B = in_sizes[0] / T_STEPS;   // I = 1
    const int last = out_size - 1;

    zero_slot_kernel<<<1, 1>>>(out, last);
    skiplstm_kernel<<<B / 2, NTH>>>(x, Wih, Whh, bg, Wp, bp, h0, c0,
                                    Wfc, bfc, out, last);
}

// round 11
// speedup vs baseline: 1.2428x; 1.2428x over previous
#include <cuda_runtime.h>

#define T_STEPS 784
#define HDIM    110
#define G4      440
#define NTH     480
#define NCLS    10

// ---------- f32x2 packed helpers ----------
__device__ __forceinline__ unsigned long long pk2(float x, float y) {
    unsigned long long r;
    asm("mov.b64 %0, {%1,%2};" : "=l"(r) : "f"(x), "f"(y));
    return r;
}
__device__ __forceinline__ float2 upk2(unsigned long long a) {
    float2 r;
    asm("mov.b64 {%0,%1}, %2;" : "=f"(r.x), "=f"(r.y) : "l"(a));
    return r;
}
__device__ __forceinline__ void ff2(unsigned long long& acc,
                                    unsigned long long a,
                                    unsigned long long b) {
    asm("fma.rn.f32x2 %0, %1, %2, %0;" : "+l"(acc) : "l"(a), "l"(b));
}

// ---------- activations ----------
__device__ __forceinline__ float tanha(float x) {          // MUFU.TANH
    float r;
    asm("tanh.approx.f32 %0, %1;" : "=f"(r) : "f"(x));
    return r;
}
__device__ __forceinline__ float sigmf(float x) {          // fast gate sigmoid
    return fmaf(0.5f, tanha(0.5f * x), 0.5f);
}
__device__ __forceinline__ float sigm_precise(float x) {   // du decision path
    return __fdividef(1.0f, 1.0f + __expf(-x));
}

__global__ void zero_slot_kernel(float* o, int idx) { o[idx] = 0.0f; }

__global__ void __launch_bounds__(NTH, 1) skiplstm_kernel(
    const float* __restrict__ x,      // [B, T, 1]
    const float* __restrict__ Wih,    // [440, 1]
    const float* __restrict__ Whh,    // [440, 110]
    const float* __restrict__ bg,     // [440]
    const float* __restrict__ Wp,     // [1, 110]
    const float* __restrict__ bp_,    // [1]
    const float* __restrict__ h0,     // [110]
    const float* __restrict__ c0,     // [110]
    const float* __restrict__ Wfc,    // [10, 110]
    const float* __restrict__ bfc,    // [10]
    float* __restrict__ out,          // [B*10 + 1]
    int last_idx)
{
    __shared__ float sx[2][T_STEPS];                 // per-batch x sequence
    __shared__ __align__(16) float smh[2][112];      // h state (pads=0)
    __shared__ __align__(16) float smc[2][112];      // c state (pads=0)
    __shared__ float smgA[G4];                       // gates, batch lane 0
    __shared__ float smgB[G4];                       // gates, batch lane 1
    __shared__ float swp[112];                       // W_p (zero-padded)
    __shared__ float swih[G4];                       // W_ih column
    __shared__ float sbj[G4];                        // gate bias

    const int tid  = threadIdx.x;
    const int warp = tid >> 5, lane = tid & 31;
    const int b0g  = blockIdx.x * 2;

    for (int i = tid; i < T_STEPS; i += NTH) {
        sx[0][i] = x[b0g * T_STEPS + i];
        sx[1][i] = x[(b0g + 1) * T_STEPS + i];
    }
    for (int i = tid; i < 112; i += NTH) {
        float hv = (i < HDIM) ? h0[i] : 0.0f;
        float cv = (i < HDIM) ? c0[i] : 0.0f;
        smh[0][i] = hv; smh[1][i] = hv;
        smc[0][i] = cv; smc[1][i] = cv;
        swp[i] = (i < HDIM) ? Wp[i] : 0.0f;
    }
    if (tid < G4) {
        swih[tid] = Wih[tid];
        sbj[tid]  = bg[tid];
    }

    // ---- GEMV warps (0-13): my gate row of W_hh, 55 f32x2 = 110 regs ----
    const bool gv = (tid < G4);
    unsigned long long w[55];
    {
        const float* wr = Whh + (gv ? tid : 0) * HDIM;
#pragma unroll
        for (int k = 0; k < 55; k++)
            w[k] = gv ? pk2(wr[2 * k], wr[2 * k + 1]) : 0ull;
    }
    const float bp = bp_[0];
    __syncthreads();

    // ---- warp-14 persistent recurrence state (per batch lane) ----
    float uu[2] = {1.0f, 1.0f};
    int   totu  = 0;

    // pointwise+du for batch lane b from gate array g at step t (warp 14)
    auto pointwise = [&](const float* g, int b) {
        const bool act = (rintf(uu[b]) != 0.0f);
        totu += act ? 1 : 0;
        float p = 0.0f;
#pragma unroll
        for (int i = 0; i < 4; i++) {
            const int d = lane + 32 * i;
            if (d < HDIM) {
                float i_ = sigmf(g[d]);
                float f_ = sigmf(g[HDIM + d]);
                float g_ = tanha(g[2 * HDIM + d]);
                float o_ = sigmf(g[3 * HDIM + d]);
                float c_old = smc[b][d];
                float cnn = f_ * c_old + i_ * g_;
                float cn  = act ? cnn : c_old;
                float hn  = act ? (o_ * tanha(cnn)) : smh[b][d];
                smc[b][d] = cn;
                smh[b][d] = hn;
                p = fmaf(cn, swp[d], p);
            }
        }
#pragma unroll
        for (int off = 16; off; off >>= 1)
            p += __shfl_xor_sync(0xffffffffu, p, off);
        float du = sigm_precise(p + bp);
        uu[b] = act ? du : uu[b] + fminf(du, 1.0f - uu[b]);
    };

    // GEMV for one batch lane into gate array g (warps 0-13)
    auto gemv = [&](const float* hsrc, float xt, float* g) {
        const ulonglong2* hq = (const ulonglong2*)hsrc;
        float xb = fmaf(xt, swih[gv ? tid : 0], sbj[gv ? tid : 0]);
        unsigned long long ax = 0ull, ay = 0ull;
#pragma unroll
        for (int k = 0; k < 27; k++) {
            ulonglong2 hv = hq[k];
            ff2(ax, w[2 * k],     hv.x);
            ff2(ay, w[2 * k + 1], hv.y);
        }
        ff2(ax, w[54], ((const unsigned long long*)hsrc)[54]);
        if (gv) {
            float2 vx = upk2(ax), vy = upk2(ay);
            g[tid] = (vx.x + vx.y) + (vy.x + vy.y) + xb;
        }
    };

    for (int t = 0; t < T_STEPS; t++) {
        // ===== PHASE A: GEMV lane0(t)  ||  pointwise lane1(t-1) =====
        if (warp < 14) {
            gemv(smh[0], sx[0][t], smgA);
        } else if (t > 0) {
            pointwise(smgB, 1);
        }
        __syncthreads();

        // ===== PHASE B: GEMV lane1(t)  ||  pointwise lane0(t) =====
        if (warp < 14) {
            gemv(smh[1], sx[1][t], smgB);
        } else {
            pointwise(smgA, 0);
        }
        __syncthreads();
    }
    // epilogue: last pointwise for lane 1 (gates of t=783)
    if (warp == 14) pointwise(smgB, 1);
    __syncthreads();

    // ---- FC head ----
    for (int pi = warp; pi < 2 * NCLS; pi += NTH / 32) {
        const int b = pi / NCLS, cls = pi % NCLS;
        const float* wf = Wfc + cls * HDIM;
        float s = 0.0f;
        for (int d = lane; d < HDIM; d += 32) s += smh[b][d] * wf[d];
#pragma unroll
        for (int off = 16; off; off >>= 1)
            s += __shfl_xor_sync(0xffffffffu, s, off);
        if (lane == 0) out[(b0g + b) * NCLS + cls] = s + bfc[cls];
    }

    // total_u (warp 14 lanes all hold identical totu; add once)
    if (warp == 14 && lane == 0) atomicAdd(&out[last_idx], (float)totu);
}

extern "C" void kernel_launch(void* const* d_in, const int* in_sizes, int n_in,
                              void* d_out, int out_size) {
    const float* x    = (const float*)d_in[0];
    const float* Wih  = (const float*)d_in[1];
    const float* Whh  = (const float*)d_in[2];
    const float* bg   = (const float*)d_in[3];
    const float* Wp   = (const float*)d_in[4];
    const float* bp   = (const float*)d_in[5];
    const float* h0   = (const float*)d_in[6];
    const float* c0   = (const float*)d_in[7];
    const float* Wfc  = (const float*)d_in[8];
    const float* bfc  = (const float*)d_in[9];
    float* out = (float*)d_out;

    const int B = in_sizes[0] / T_STEPS;   // I = 1
    const int last = out_size - 1;

    zero_slot_kernel<<<1, 1>>>(out, last);
    skiplstm_kernel<<<B / 2, NTH>>>(x, Wih, Whh, bg, Wp, bp, h0, c0,
                                    Wfc, bfc, out, last);
}